// round 4
// baseline (speedup 1.0000x reference)
#include <cuda_runtime.h>
#include <math.h>

#define NN 50000
#define EE 800000
#define FDIM 256   /* HEADS*HID */

// ---------------- scratch (device globals: allowed) ----------------
__device__ float g_ft[(size_t)NN * FDIM];
__device__ float g_x [(size_t)NN * FDIM];
__device__ float g_res[(size_t)NN * FDIM];
__device__ float g_el[NN * 4];
__device__ float g_er[NN * 4];
__device__ float g_hf[NN * 64];
__device__ int   g_deg[NN + 1];
__device__ int   g_off[NN + 1];
__device__ int   g_pos[NN];
__device__ int   g_esrc[EE];

__device__ __forceinline__ float lrelu(float x) { return x > 0.f ? x : 0.2f * x; }

// ---------------- CSR build ----------------
__global__ void zero_int_kernel(int* __restrict__ p, int n) {
    int i = blockIdx.x * blockDim.x + threadIdx.x;
    if (i < n) p[i] = 0;
}

__global__ void hist_kernel(const int* __restrict__ dst, int* __restrict__ deg, int e) {
    int i = blockIdx.x * blockDim.x + threadIdx.x;
    if (i < e) atomicAdd(&deg[dst[i]], 1);
}

__global__ void scan_kernel(const int* __restrict__ deg, int* __restrict__ off,
                            int* __restrict__ pos, int n) {
    __shared__ int sh[1024];
    int running = 0;
    for (int base = 0; base < n; base += 1024) {
        int i = base + threadIdx.x;
        int v = (i < n) ? deg[i] : 0;
        sh[threadIdx.x] = v;
        __syncthreads();
        for (int o = 1; o < 1024; o <<= 1) {
            int t = (threadIdx.x >= o) ? sh[threadIdx.x - o] : 0;
            __syncthreads();
            sh[threadIdx.x] += t;
            __syncthreads();
        }
        int excl = sh[threadIdx.x] - v;
        if (i < n) { off[i] = running + excl; pos[i] = running + excl; }
        running += sh[1023];
        __syncthreads();
    }
    if (threadIdx.x == 0) off[n] = running;
}

__global__ void scatter_kernel(const int* __restrict__ src, const int* __restrict__ dst,
                               int* __restrict__ pos, int* __restrict__ esrc, int e) {
    int i = blockIdx.x * blockDim.x + threadIdx.x;
    if (i < e) {
        int p = atomicAdd(&pos[dst[i]], 1);
        esrc[p] = src[i];
    }
}

// ---------------- tiled GEMM + fused attention-logit epilogue ----------------
// Y[M,256] = X[M,K] @ W[K,256]. BM=128, BN=128, BK=32, 8x8 reg tile.
// Register prefetch double-buffer on the K loop.
// EL: block covers 2 heads (bn>>6, +1); compute el/er via half-warp reduce.
template <int K, bool EL>
__global__ void __launch_bounds__(256) gemm_tiled(
    const float* __restrict__ X, const float* __restrict__ W,
    float* __restrict__ Y,
    const float* __restrict__ al, const float* __restrict__ ar,
    float* __restrict__ el, float* __restrict__ er, int M)
{
    __shared__ float sX[32][132];
    __shared__ float sW[32][128];

    const int t  = threadIdx.x;
    const int tx = t & 15;
    const int ty = t >> 4;
    const int bm = blockIdx.x * 128;
    const int bn = blockIdx.y * 128;

    // per-thread load coordinates (4 float4 each for X and W tiles)
    int xrow[4], xkk[4], wkk[4], wnn[4];
    #pragma unroll
    for (int l = 0; l < 4; l++) {
        int idx = t + l * 256;
        xrow[l] = idx >> 3;
        xkk[l]  = (idx & 7) * 4;
        wkk[l]  = idx >> 5;
        wnn[l]  = (idx & 31) * 4;
    }

    float4 rx[4], rw[4];
    // preload chunk 0
    #pragma unroll
    for (int l = 0; l < 4; l++) {
        int gr = bm + xrow[l];
        rx[l] = (gr < M) ? *(const float4*)(X + (size_t)gr * K + xkk[l])
                         : make_float4(0.f, 0.f, 0.f, 0.f);
        rw[l] = *(const float4*)(W + (size_t)wkk[l] * 256 + bn + wnn[l]);
    }
    #pragma unroll
    for (int l = 0; l < 4; l++) {
        sX[xkk[l] + 0][xrow[l]] = rx[l].x; sX[xkk[l] + 1][xrow[l]] = rx[l].y;
        sX[xkk[l] + 2][xrow[l]] = rx[l].z; sX[xkk[l] + 3][xrow[l]] = rx[l].w;
        *(float4*)&sW[wkk[l]][wnn[l]] = rw[l];
    }
    __syncthreads();

    float acc[8][8];
    #pragma unroll
    for (int i = 0; i < 8; i++)
        #pragma unroll
        for (int j = 0; j < 8; j++) acc[i][j] = 0.f;

    for (int k0 = 0; k0 < K; k0 += 32) {
        bool more = (k0 + 32 < K);
        if (more) {
            #pragma unroll
            for (int l = 0; l < 4; l++) {
                int gr = bm + xrow[l];
                rx[l] = (gr < M) ? *(const float4*)(X + (size_t)gr * K + k0 + 32 + xkk[l])
                                 : make_float4(0.f, 0.f, 0.f, 0.f);
                rw[l] = *(const float4*)(W + (size_t)(k0 + 32 + wkk[l]) * 256 + bn + wnn[l]);
            }
        }

        #pragma unroll
        for (int k = 0; k < 32; k++) {
            float4 a0 = *(const float4*)&sX[k][ty * 8];
            float4 a1 = *(const float4*)&sX[k][ty * 8 + 4];
            float4 b0 = *(const float4*)&sW[k][tx * 4];
            float4 b1 = *(const float4*)&sW[k][64 + tx * 4];
            float a[8] = {a0.x, a0.y, a0.z, a0.w, a1.x, a1.y, a1.z, a1.w};
            float b[8] = {b0.x, b0.y, b0.z, b0.w, b1.x, b1.y, b1.z, b1.w};
            #pragma unroll
            for (int i = 0; i < 8; i++)
                #pragma unroll
                for (int j = 0; j < 8; j++)
                    acc[i][j] = fmaf(a[i], b[j], acc[i][j]);
        }
        __syncthreads();
        if (more) {
            #pragma unroll
            for (int l = 0; l < 4; l++) {
                sX[xkk[l] + 0][xrow[l]] = rx[l].x; sX[xkk[l] + 1][xrow[l]] = rx[l].y;
                sX[xkk[l] + 2][xrow[l]] = rx[l].z; sX[xkk[l] + 3][xrow[l]] = rx[l].w;
                *(float4*)&sW[wkk[l]][wnn[l]] = rw[l];
            }
            __syncthreads();
        }
    }

    #pragma unroll
    for (int i = 0; i < 8; i++) {
        int gr = bm + ty * 8 + i;
        if (gr < M) {
            float4* yb = (float4*)(Y + (size_t)gr * 256 + bn);
            yb[tx]      = make_float4(acc[i][0], acc[i][1], acc[i][2], acc[i][3]);
            yb[16 + tx] = make_float4(acc[i][4], acc[i][5], acc[i][6], acc[i][7]);
        }
    }

    if (EL) {
        const int h0 = bn >> 6;   // heads h0, h0+1 in this block
        float al0[4], al1[4], ar0[4], ar1[4];
        #pragma unroll
        for (int j = 0; j < 4; j++) {
            al0[j] = al[h0 * 64 + tx * 4 + j];
            al1[j] = al[(h0 + 1) * 64 + tx * 4 + j];
            ar0[j] = ar[h0 * 64 + tx * 4 + j];
            ar1[j] = ar[(h0 + 1) * 64 + tx * 4 + j];
        }
        #pragma unroll
        for (int i = 0; i < 8; i++) {
            float sl0 = 0.f, sl1 = 0.f, sr0 = 0.f, sr1 = 0.f;
            #pragma unroll
            for (int j = 0; j < 4; j++) {
                sl0 = fmaf(acc[i][j],     al0[j], sl0);
                sr0 = fmaf(acc[i][j],     ar0[j], sr0);
                sl1 = fmaf(acc[i][4 + j], al1[j], sl1);
                sr1 = fmaf(acc[i][4 + j], ar1[j], sr1);
            }
            #pragma unroll
            for (int o = 8; o; o >>= 1) {
                sl0 += __shfl_xor_sync(0xffffffffu, sl0, o);
                sl1 += __shfl_xor_sync(0xffffffffu, sl1, o);
                sr0 += __shfl_xor_sync(0xffffffffu, sr0, o);
                sr1 += __shfl_xor_sync(0xffffffffu, sr1, o);
            }
            if (tx == 0) {
                int gr = bm + ty * 8 + i;
                if (gr < M) {
                    el[gr * 4 + h0]     = sl0;
                    el[gr * 4 + h0 + 1] = sl1;
                    er[gr * 4 + h0]     = sr0;
                    er[gr * 4 + h0 + 1] = sr1;
                }
            }
        }
    }
}

// ---------------- per-destination softmax aggregation ----------------
// 2 warps per node (each owns 128 features = 2 heads, 1 float4/lane/edge).
// Pass 1: warp-parallel max; pass 2: 4-deep unrolled edge pipeline.
template <int MODE>  // 0: relu, write [N,256] ; 1: final, head-mean -> [N,64]
__global__ void __launch_bounds__(256) agg_kernel(
    const int* __restrict__ off, const int* __restrict__ esrc,
    const float* __restrict__ el, const float* __restrict__ er,
    const float* __restrict__ ft, const float* __restrict__ resid,
    float* __restrict__ out, int n)
{
    const int t    = threadIdx.x;
    const int warp = t >> 5;           // 0..7
    const int lane = t & 31;
    const int nl   = warp >> 1;        // node slot in block: 0..3
    const int half = warp & 1;         // feature half
    const int nid  = blockIdx.x * 4 + nl;
    const bool active = (nid < n);

    __shared__ float4 smA[4][16];
    __shared__ float4 smB[4][16];

    float v0 = 0.f, v1 = 0.f, v2 = 0.f, v3 = 0.f;

    if (active) {
        const int s = off[nid], eEnd = off[nid + 1];
        float2 erp = *(const float2*)(er + nid * 4 + half * 2);

        // pass 1: max over edges for this half's two heads
        float mxa = -1e30f, mxb = -1e30f;
        for (int i = s + lane; i < eEnd; i += 32) {
            int sc = esrc[i];
            float2 ep = *(const float2*)(el + sc * 4 + half * 2);
            mxa = fmaxf(mxa, lrelu(ep.x + erp.x));
            mxb = fmaxf(mxb, lrelu(ep.y + erp.y));
        }
        #pragma unroll
        for (int o = 16; o; o >>= 1) {
            mxa = fmaxf(mxa, __shfl_xor_sync(0xffffffffu, mxa, o));
            mxb = fmaxf(mxb, __shfl_xor_sync(0xffffffffu, mxb, o));
        }

        const float m_h  = (lane < 16) ? mxa : mxb;
        const float er_h = (lane < 16) ? erp.x : erp.y;
        const int   hOff = half * 2 + (lane >> 4);   // this lane's head
        const int   fidx = half * 32 + lane;         // float4 index in [0,64)

        float den = 0.f;
        float a0 = 0.f, a1 = 0.f, a2 = 0.f, a3 = 0.f;
        const float4* ft4 = (const float4*)ft;

        int i = s;
        for (; i + 3 < eEnd; i += 4) {
            int sc0 = __ldg(esrc + i);
            int sc1 = __ldg(esrc + i + 1);
            int sc2 = __ldg(esrc + i + 2);
            int sc3 = __ldg(esrc + i + 3);
            float e0 = __ldg(el + sc0 * 4 + hOff);
            float e1 = __ldg(el + sc1 * 4 + hOff);
            float e2 = __ldg(el + sc2 * 4 + hOff);
            float e3 = __ldg(el + sc3 * 4 + hOff);
            float4 f0 = ft4[(size_t)sc0 * 64 + fidx];
            float4 f1 = ft4[(size_t)sc1 * 64 + fidx];
            float4 f2 = ft4[(size_t)sc2 * 64 + fidx];
            float4 f3 = ft4[(size_t)sc3 * 64 + fidx];
            float x0 = __expf(lrelu(e0 + er_h) - m_h);
            float x1 = __expf(lrelu(e1 + er_h) - m_h);
            float x2 = __expf(lrelu(e2 + er_h) - m_h);
            float x3 = __expf(lrelu(e3 + er_h) - m_h);
            den += (x0 + x1) + (x2 + x3);
            a0 = fmaf(x0, f0.x, a0); a1 = fmaf(x0, f0.y, a1);
            a2 = fmaf(x0, f0.z, a2); a3 = fmaf(x0, f0.w, a3);
            a0 = fmaf(x1, f1.x, a0); a1 = fmaf(x1, f1.y, a1);
            a2 = fmaf(x1, f1.z, a2); a3 = fmaf(x1, f1.w, a3);
            a0 = fmaf(x2, f2.x, a0); a1 = fmaf(x2, f2.y, a1);
            a2 = fmaf(x2, f2.z, a2); a3 = fmaf(x2, f2.w, a3);
            a0 = fmaf(x3, f3.x, a0); a1 = fmaf(x3, f3.y, a1);
            a2 = fmaf(x3, f3.z, a2); a3 = fmaf(x3, f3.w, a3);
        }
        for (; i < eEnd; i++) {
            int sc = __ldg(esrc + i);
            float ev = lrelu(__ldg(el + sc * 4 + hOff) + er_h);
            float ex = __expf(ev - m_h);
            den += ex;
            float4 f = ft4[(size_t)sc * 64 + fidx];
            a0 = fmaf(ex, f.x, a0); a1 = fmaf(ex, f.y, a1);
            a2 = fmaf(ex, f.z, a2); a3 = fmaf(ex, f.w, a3);
        }

        float inv = (eEnd > s) ? (1.0f / den) : 0.f;
        float4 r = *(const float4*)(resid + (size_t)nid * FDIM + half * 128 + lane * 4);
        v0 = fmaf(a0, inv, r.x);
        v1 = fmaf(a1, inv, r.y);
        v2 = fmaf(a2, inv, r.z);
        v3 = fmaf(a3, inv, r.w);
    }

    if (MODE == 0) {
        if (active) {
            v0 = fmaxf(v0, 0.f); v1 = fmaxf(v1, 0.f);
            v2 = fmaxf(v2, 0.f); v3 = fmaxf(v3, 0.f);
            *(float4*)(out + (size_t)nid * FDIM + half * 128 + lane * 4) =
                make_float4(v0, v1, v2, v3);
        }
    } else {
        // combine the 2 heads within this warp (lane l <-> l+16 hold same dims)
        v0 += __shfl_xor_sync(0xffffffffu, v0, 16);
        v1 += __shfl_xor_sync(0xffffffffu, v1, 16);
        v2 += __shfl_xor_sync(0xffffffffu, v2, 16);
        v3 += __shfl_xor_sync(0xffffffffu, v3, 16);
        if (lane < 16) {
            if (half) smB[nl][lane] = make_float4(v0, v1, v2, v3);
            else      smA[nl][lane] = make_float4(v0, v1, v2, v3);
        }
        __syncthreads();
        if (half == 0 && lane < 16 && active) {
            float4 a = smA[nl][lane], b = smB[nl][lane];
            *(float4*)(out + (size_t)nid * 64 + lane * 4) =
                make_float4((a.x + b.x) * 0.25f, (a.y + b.y) * 0.25f,
                            (a.z + b.z) * 0.25f, (a.w + b.w) * 0.25f);
        }
    }
}

// ---------------- edge scoring MLP as register-tiled GEMM ----------------
__global__ void __launch_bounds__(256) mlp_kernel(
    const float* __restrict__ hf, const int* __restrict__ src,
    const int* __restrict__ dst, const float* __restrict__ Wm1,
    const float* __restrict__ bm1, const float* __restrict__ Wm2,
    const float* __restrict__ bm2, float* __restrict__ out, int e)
{
    __shared__ float sD[64][68];
    __shared__ float sW[64][64];
    __shared__ float sb[64];
    __shared__ float sW2[64];

    const int t    = threadIdx.x;
    const int warp = t >> 5;
    const int lane = t & 31;
    const int e0   = blockIdx.x * 64;

    for (int i = t; i < 64 * 64; i += 256) sW[i >> 6][i & 63] = Wm1[i];
    if (t < 64) { sb[t] = bm1[t]; sW2[t] = Wm2[t]; }

    #pragma unroll
    for (int j = 0; j < 8; j++) {
        int le  = warp * 8 + j;
        int eid = e0 + le;
        float2 dv;
        if (eid < e) {
            int s = src[eid], d = dst[eid];
            float2 a = *(const float2*)(hf + (size_t)s * 64 + lane * 2);
            float2 b = *(const float2*)(hf + (size_t)d * 64 + lane * 2);
            dv.x = fabsf(a.x - b.x);
            dv.y = fabsf(a.y - b.y);
        } else {
            dv.x = 0.f; dv.y = 0.f;
        }
        *(float2*)&sD[le][lane * 2] = dv;
    }
    __syncthreads();

    const int tx = t & 15;
    const int ty = t >> 4;

    float z[4][4];
    #pragma unroll
    for (int i = 0; i < 4; i++)
        #pragma unroll
        for (int j = 0; j < 4; j++) z[i][j] = sb[tx * 4 + j];

    #pragma unroll 8
    for (int k = 0; k < 64; k++) {
        float4 wv = *(const float4*)&sW[k][tx * 4];
        float d0 = sD[ty * 4 + 0][k];
        float d1 = sD[ty * 4 + 1][k];
        float d2 = sD[ty * 4 + 2][k];
        float d3 = sD[ty * 4 + 3][k];
        z[0][0] = fmaf(d0, wv.x, z[0][0]); z[0][1] = fmaf(d0, wv.y, z[0][1]);
        z[0][2] = fmaf(d0, wv.z, z[0][2]); z[0][3] = fmaf(d0, wv.w, z[0][3]);
        z[1][0] = fmaf(d1, wv.x, z[1][0]); z[1][1] = fmaf(d1, wv.y, z[1][1]);
        z[1][2] = fmaf(d1, wv.z, z[1][2]); z[1][3] = fmaf(d1, wv.w, z[1][3]);
        z[2][0] = fmaf(d2, wv.x, z[2][0]); z[2][1] = fmaf(d2, wv.y, z[2][1]);
        z[2][2] = fmaf(d2, wv.z, z[2][2]); z[2][3] = fmaf(d2, wv.w, z[2][3]);
        z[3][0] = fmaf(d3, wv.x, z[3][0]); z[3][1] = fmaf(d3, wv.y, z[3][1]);
        z[3][2] = fmaf(d3, wv.z, z[3][2]); z[3][3] = fmaf(d3, wv.w, z[3][3]);
    }

    float w2a = sW2[tx * 4 + 0], w2b = sW2[tx * 4 + 1];
    float w2c = sW2[tx * 4 + 2], w2d = sW2[tx * 4 + 3];
    float p[4];
    #pragma unroll
    for (int i = 0; i < 4; i++) {
        p[i] = fmaxf(z[i][0], 0.f) * w2a + fmaxf(z[i][1], 0.f) * w2b
             + fmaxf(z[i][2], 0.f) * w2c + fmaxf(z[i][3], 0.f) * w2d;
        #pragma unroll
        for (int o = 8; o; o >>= 1) p[i] += __shfl_xor_sync(0xffffffffu, p[i], o);
    }
    if (tx == 0) {
        float b2 = bm2[0];
        #pragma unroll
        for (int i = 0; i < 4; i++) {
            int eid = e0 + ty * 4 + i;
            if (eid < e) out[eid] = 1.0f / (1.0f + __expf(-(p[i] + b2)));
        }
    }
}

// ---------------- launch ----------------
extern "C" void kernel_launch(void* const* d_in, const int* in_sizes, int n_in,
                              void* d_out, int out_size)
{
    const float* h   = (const float*)d_in[0];
    const int*   src = (const int*)d_in[1];
    const int*   dst = (const int*)d_in[2];
    const float* W1  = (const float*)d_in[3];
    const float* Wr1 = (const float*)d_in[4];
    const float* al1 = (const float*)d_in[5];
    const float* ar1 = (const float*)d_in[6];
    const float* W2  = (const float*)d_in[7];
    const float* al2 = (const float*)d_in[8];
    const float* ar2 = (const float*)d_in[9];
    const float* W3  = (const float*)d_in[10];
    const float* al3 = (const float*)d_in[11];
    const float* ar3 = (const float*)d_in[12];
    const float* Wm1 = (const float*)d_in[13];
    const float* bm1 = (const float*)d_in[14];
    const float* Wm2 = (const float*)d_in[15];
    const float* bm2 = (const float*)d_in[16];
    float* out = (float*)d_out;

    const int n = in_sizes[0] / 128;   // 50000
    const int e = in_sizes[1];         // 800000

    float *ft, *x, *res, *el, *er, *hfp;
    int *deg, *off, *pos, *esrc;
    cudaGetSymbolAddress((void**)&ft,   g_ft);
    cudaGetSymbolAddress((void**)&x,    g_x);
    cudaGetSymbolAddress((void**)&res,  g_res);
    cudaGetSymbolAddress((void**)&el,   g_el);
    cudaGetSymbolAddress((void**)&er,   g_er);
    cudaGetSymbolAddress((void**)&hfp,  g_hf);
    cudaGetSymbolAddress((void**)&deg,  g_deg);
    cudaGetSymbolAddress((void**)&off,  g_off);
    cudaGetSymbolAddress((void**)&pos,  g_pos);
    cudaGetSymbolAddress((void**)&esrc, g_esrc);

    // CSR build (dst-sorted edges)
    zero_int_kernel<<<(n + 1 + 255) / 256, 256>>>(deg, n + 1);
    hist_kernel<<<(e + 255) / 256, 256>>>(dst, deg, e);
    scan_kernel<<<1, 1024>>>(deg, off, pos, n);
    scatter_kernel<<<(e + 255) / 256, 256>>>(src, dst, pos, esrc, e);

    dim3 gg((n + 127) / 128, 2);
    const int ga = (n + 3) / 4;   // agg: 2 warps/node, 4 nodes/block

    // Layer 1
    gemm_tiled<128, true ><<<gg, 256>>>(h, W1,  ft,  al1, ar1, el, er, n);
    gemm_tiled<128, false><<<gg, 256>>>(h, Wr1, res, nullptr, nullptr, nullptr, nullptr, n);
    agg_kernel<0><<<ga, 256>>>(off, esrc, el, er, ft, res, x, n);
    // Layer 2 (identity residual)
    gemm_tiled<256, true><<<gg, 256>>>(x, W2, ft, al2, ar2, el, er, n);
    agg_kernel<0><<<ga, 256>>>(off, esrc, el, er, ft, x, x, n);
    // Layer 3 (identity residual, no activation, head-mean -> hf)
    gemm_tiled<256, true><<<gg, 256>>>(x, W3, ft, al3, ar3, el, er, n);
    agg_kernel<1><<<ga, 256>>>(off, esrc, el, er, ft, x, hfp, n);

    // Edge MLP -> scores
    mlp_kernel<<<(e + 63) / 64, 256>>>(hfp, src, dst, Wm1, bm1, Wm2, bm2, out, e);
}